// round 14
// baseline (speedup 1.0000x reference)
#include <cuda_runtime.h>

// ---------------- problem constants ----------------
#define N_ATOMS     20000
#define N_EDGES     640000
#define N_ANG_EDGES 160000
#define N_PAIRS     560000
#define N_FEAT      407        // 87 onehot + 64 radial + 256 angular

// ---------------- packed f32x2 helpers (Blackwell FFMA2 path) ----------------
__device__ __forceinline__ unsigned long long pk2(float lo, float hi) {
    unsigned long long r;
    asm("mov.b64 %0, {%1, %2};"
        : "=l"(r) : "r"(__float_as_uint(lo)), "r"(__float_as_uint(hi)));
    return r;
}
__device__ __forceinline__ unsigned long long mul2(unsigned long long a, unsigned long long b) {
    unsigned long long r;
    asm("mul.rn.f32x2 %0, %1, %2;" : "=l"(r) : "l"(a), "l"(b));
    return r;
}
__device__ __forceinline__ unsigned long long fma2(unsigned long long a, unsigned long long b,
                                                   unsigned long long c) {
    unsigned long long r;
    asm("fma.rn.f32x2 %0, %1, %2, %3;" : "=l"(r) : "l"(a), "l"(b), "l"(c));
    return r;
}
__device__ __forceinline__ void upk2(unsigned long long v, float& lo, float& hi) {
    unsigned int a, b;
    asm("mov.b64 {%0, %1}, %2;" : "=r"(a), "=r"(b) : "l"(v));
    lo = __uint_as_float(a);
    hi = __uint_as_float(b);
}

// ---------------- device scratch (allocation-free rule) ----------------
__device__ __align__(16) float  g_val    [N_ATOMS * 4];     // per-atom valence (320KB)
__device__ __align__(8)  float2 g_edge_ds[N_ANG_EDGES];     // {d, sw}
__device__ __align__(16) float4 g_edge_v [N_ANG_EDGES];     // valence of ang dst
__device__ int g_cnt_r [N_ATOMS];
__device__ int g_off_r [N_ATOMS + 1];
__device__ int g_cnt_a [N_ATOMS];
__device__ int g_off_a [N_ATOMS + 1];
__device__ int g_rank_r[N_EDGES];
__device__ int g_rank_a[N_PAIRS];
__device__ int g_task;
__device__ __align__(16) float4 g_pay_r[N_EDGES];           // {d, 0.25*sw, as_float(dst), 0}
__device__ __align__(16) float4 g_pay_a[N_PAIRS * 4];       // {f1[4], f2sw[4], vp[4], vm[4]}

// ---------------- kernels ----------------

// valence gather + angular-edge structs + histograms (ranks saved for scatter)
__global__ void k_prep(const int* __restrict__ species,
                       const float* __restrict__ vtab,
                       const int* __restrict__ ang_dst,
                       const float* __restrict__ ang_d,
                       const float* __restrict__ ang_sw,
                       const int* __restrict__ catom,
                       const int* __restrict__ esrc) {
    int idx = blockIdx.x * blockDim.x + threadIdx.x;
    int stride = gridDim.x * blockDim.x;
    for (int t = idx; t < N_ATOMS; t += stride) {
        int sp = species[t];
        ((float4*)g_val)[t] = *(const float4*)(vtab + sp * 4);
    }
    for (int t = idx; t < N_ANG_EDGES; t += stride) {
        int dst = ang_dst[t];
        int sp  = species[dst];
        g_edge_v[t]  = *(const float4*)(vtab + sp * 4);
        g_edge_ds[t] = make_float2(ang_d[t], ang_sw[t]);
    }
    for (int t = idx; t < N_PAIRS; t += stride)
        g_rank_a[t] = atomicAdd(&g_cnt_a[catom[t]], 1);
    for (int t = idx; t < N_EDGES; t += stride)
        g_rank_r[t] = atomicAdd(&g_cnt_r[esrc[t]], 1);
}

// two-block exclusive scan: block 0 -> radial counts, block 1 -> angular counts
__global__ void k_scan() {
    const int CHUNK = 20;                 // 1024 * 20 = 20480 >= N_ATOMS
    __shared__ int warp_sums[32];
    const int* cnt = (blockIdx.x == 0) ? g_cnt_r : g_cnt_a;
    int* off       = (blockIdx.x == 0) ? g_off_r : g_off_a;

    int t = threadIdx.x;
    int base = t * CHUNK;
    int local[CHUNK];
    int sum = 0;
    #pragma unroll
    for (int u = 0; u < CHUNK; u++) {
        int i = base + u;
        int v = (i < N_ATOMS) ? cnt[i] : 0;
        local[u] = sum;
        sum += v;
    }
    int lane = t & 31, wid = t >> 5;
    int incl = sum;
    #pragma unroll
    for (int offt = 1; offt < 32; offt <<= 1) {
        int x = __shfl_up_sync(0xFFFFFFFFu, incl, offt);
        if (lane >= offt) incl += x;
    }
    if (lane == 31) warp_sums[wid] = incl;
    __syncthreads();
    if (wid == 0) {
        int w = warp_sums[lane];
        #pragma unroll
        for (int offt = 1; offt < 32; offt <<= 1) {
            int x = __shfl_up_sync(0xFFFFFFFFu, w, offt);
            if (lane >= offt) w += x;
        }
        warp_sums[lane] = w;
    }
    __syncthreads();
    int excl_base = incl - sum + (wid > 0 ? warp_sums[wid - 1] : 0);
    #pragma unroll
    for (int u = 0; u < CHUNK; u++) {
        int i = base + u;
        if (i < N_ATOMS) off[i] = excl_base + local[u];
    }
    if (t == 1023) off[N_ATOMS] = excl_base + sum;
}

// fused scatter (no atomics): radial edges -> 16B payload, angular pairs -> 64B payload
__global__ void k_scatter(const float* __restrict__ dist,
                          const float* __restrict__ swc,
                          const int* __restrict__ esrc,
                          const int* __restrict__ edst,
                          const float* __restrict__ angles,
                          const int* __restrict__ pasrc,
                          const int* __restrict__ padst,
                          const int* __restrict__ catom) {
    int idx = blockIdx.x * blockDim.x + threadIdx.x;
    int stride = gridDim.x * blockDim.x;

    // ---- radial edges: 16B payload {d, s, dst_id} ----
    for (int e = idx; e < N_EDGES; e += stride) {
        float d = dist[e];
        float s = 0.25f * swc[e];
        int a   = esrc[e];
        int pos = g_off_r[a] + g_rank_r[e];
        g_pay_r[pos] = make_float4(d, s, __int_as_float(edst[e]), 0.f);
    }

    // ---- angular pairs: 64B payload ----
    for (int p = idx; p < N_PAIRS; p += stride) {
        int ea = pasrc[p];
        int eb = padst[p];
        float2 Ads = g_edge_ds[ea];
        float2 Bds = g_edge_ds[eb];
        float4 Av  = g_edge_v[ea];
        float4 Bv  = g_edge_v[eb];

        float d12 = 0.5f * (Ads.x + Bds.x);
        float swp = 2.0f * Ads.y * Bds.y;

        float sn, cs;
        __sincosf(angles[p], &sn, &cs);
        const float CZ[4] = { 0.92387953f,  0.38268343f, -0.38268343f, -0.92387953f};
        const float SZ[4] = { 0.38268343f,  0.92387953f,  0.92387953f,  0.38268343f};
        float f1[4];
        #pragma unroll
        for (int k = 0; k < 4; k++) {
            float u = 0.5f + 0.5f * (cs * CZ[k] + sn * SZ[k]);
            float u2 = u * u, u4 = u2 * u2, u8 = u4 * u4, u16 = u8 * u8;
            f1[k] = u16 * u16;
        }
        float f2[4];
        #pragma unroll
        for (int a = 0; a < 4; a++) {
            float x = d12 - (0.8f + 0.675f * (float)a);
            f2[a] = swp * __expf(-8.0f * x * x);
        }

        int c = catom[p];
        int pos = g_off_a[c] + g_rank_a[p];
        float4* P = g_pay_a + pos * 4;
        P[0] = make_float4(f1[0], f1[1], f1[2], f1[3]);
        P[1] = make_float4(f2[0], f2[1], f2[2], f2[3]);
        P[2] = make_float4(Av.x + Bv.x, Av.y + Bv.y, Av.z + Bv.z, Av.w + Bv.w);
        P[3] = make_float4(Av.x * Bv.x, Av.y * Bv.y, Av.z * Bv.z, Av.w * Bv.w);
    }
}

// fused gather: warp-per-atom, dynamic queue (REVERSED order for L2 recency),
// pointer-walking loops.
// Radial: full-warp broadcast, 3x batched.
// Angular: split-warp, 2x batched, packed f32x2 accumulation — 16 cell
//   accumulators live as 8 f32x2 regs; per pair 2 packed muls + 8 packed FMAs.
//   Lane t=lane&15 covers vcombo (ii,jj) for all 16 cells; halves merged via
//   shfl_xor(16); lane (g,t) writes cells [g*8,g*8+8) at col 151 + c*16 + t.
__global__ void __launch_bounds__(256, 5) k_gather(const int* __restrict__ species,
                                                   float* __restrict__ out) {
    int lane = threadIdx.x & 31;
    int g  = lane >> 4;
    int t  = lane & 15;
    int ii = t >> 2;
    int jj = t & 3;
    int iq = lane & 3;
    float sh1 = 0.8f + 0.275f * (float)(lane >> 2);
    float sh2 = sh1 + 2.2f;                          // +8 bins * 0.275

    for (;;) {
        int a;
        if (lane == 0) a = atomicAdd(&g_task, 1);
        a = __shfl_sync(0xFFFFFFFFu, a, 0);
        if (a >= N_ATOMS) return;
        a = N_ATOMS - 1 - a;                         // reverse: read newest payload first

        float* o = out + (size_t)a * N_FEAT;

        // ---- onehot ----
        int sp = species[a];
        for (int c = lane; c < 87; c += 32) o[c] = (c == sp) ? 1.0f : 0.0f;

        // ---- radial: cols 87..150 (pointer walk, 3x batch) ----
        int s0 = g_off_r[a];
        int n0 = g_off_r[a + 1] - s0;
        const float4* rp = g_pay_r + s0;
        float acc0 = 0.f, acc1 = 0.f;
        int p = 0;
        for (; p + 3 <= n0; p += 3, rp += 3) {
            float4 Pa = rp[0];
            float4 Pb = rp[1];
            float4 Pc = rp[2];
            float va = g_val[__float_as_int(Pa.z) * 4 + iq];
            float vb = g_val[__float_as_int(Pb.z) * 4 + iq];
            float vc = g_val[__float_as_int(Pc.z) * 4 + iq];
            float xa1 = Pa.x - sh1, xa2 = Pa.x - sh2;
            float xb1 = Pb.x - sh1, xb2 = Pb.x - sh2;
            float xc1 = Pc.x - sh1, xc2 = Pc.x - sh2;
            acc0 = fmaf(Pa.y * __expf(-16.f * xa1 * xa1), va, acc0);
            acc1 = fmaf(Pa.y * __expf(-16.f * xa2 * xa2), va, acc1);
            acc0 = fmaf(Pb.y * __expf(-16.f * xb1 * xb1), vb, acc0);
            acc1 = fmaf(Pb.y * __expf(-16.f * xb2 * xb2), vb, acc1);
            acc0 = fmaf(Pc.y * __expf(-16.f * xc1 * xc1), vc, acc0);
            acc1 = fmaf(Pc.y * __expf(-16.f * xc2 * xc2), vc, acc1);
        }
        for (; p < n0; p++, rp++) {
            float4 Pa = rp[0];
            float va = g_val[__float_as_int(Pa.z) * 4 + iq];
            float xa1 = Pa.x - sh1, xa2 = Pa.x - sh2;
            acc0 = fmaf(Pa.y * __expf(-16.f * xa1 * xa1), va, acc0);
            acc1 = fmaf(Pa.y * __expf(-16.f * xa2 * xa2), va, acc1);
        }
        o[87 + lane]  = acc0;
        o[119 + lane] = acc1;

        // ---- angular: cols 151..406 (split-warp, 2x batch, packed f32x2) ----
        int s1 = g_off_a[a];
        int n1 = g_off_a[a + 1] - s1;
        // acc2[a2*2+j] packs cells (a2*4+2j, a2*4+2j+1)
        unsigned long long acc2[8];
        #pragma unroll
        for (int q = 0; q < 8; q++) acc2[q] = 0ULL;

        // half g processes pairs g, g+2, ... : cnt = ceil((n1-g)/2)
        int cnt = (n1 - g + 1) >> 1;
        const float* bp = (const float*)g_pay_a + ((size_t)(s1 + g) << 4);

        #define ANG_BODY(P)                                                     \
        {                                                                       \
            float4 F1 = *(const float4*)(P);                                    \
            float4 F2 = *(const float4*)((P) + 4);                              \
            float wv = (P)[8 + ii] * (P)[12 + jj];                              \
            unsigned long long wv2 = pk2(wv, wv);                               \
            unsigned long long w01 = mul2(pk2(F1.x, F1.y), wv2);                \
            unsigned long long w23 = mul2(pk2(F1.z, F1.w), wv2);                \
            unsigned long long f2x = pk2(F2.x, F2.x);                           \
            unsigned long long f2y = pk2(F2.y, F2.y);                           \
            unsigned long long f2z = pk2(F2.z, F2.z);                           \
            unsigned long long f2w = pk2(F2.w, F2.w);                           \
            acc2[0] = fma2(w01, f2x, acc2[0]);                                  \
            acc2[1] = fma2(w23, f2x, acc2[1]);                                  \
            acc2[2] = fma2(w01, f2y, acc2[2]);                                  \
            acc2[3] = fma2(w23, f2y, acc2[3]);                                  \
            acc2[4] = fma2(w01, f2z, acc2[4]);                                  \
            acc2[5] = fma2(w23, f2z, acc2[5]);                                  \
            acc2[6] = fma2(w01, f2w, acc2[6]);                                  \
            acc2[7] = fma2(w23, f2w, acc2[7]);                                  \
        }

        int it = 0;
        for (; it + 2 <= cnt; it += 2, bp += 64) {
            ANG_BODY(bp)
            ANG_BODY(bp + 32)
        }
        for (; it < cnt; it++, bp += 32) {
            ANG_BODY(bp)
        }
        #undef ANG_BODY

        // unpack: q -> cells (2q, 2q+1); acc[c] with c = a2*4+k ordering preserved
        float acc[16];
        #pragma unroll
        for (int q = 0; q < 8; q++) upk2(acc2[q], acc[2 * q], acc[2 * q + 1]);

        // merge halves (lanes reconverged after loop)
        #pragma unroll
        for (int c = 0; c < 16; c++)
            acc[c] += __shfl_xor_sync(0xFFFFFFFFu, acc[c], 16);
        // lane (g,t) writes cells c in [g*8, g*8+8): col 151 + c*16 + t
        #pragma unroll
        for (int c2 = 0; c2 < 8; c2++) {
            int c = g * 8 + c2;
            o[151 + c * 16 + t] = acc[c];
        }
    }
}

// ---------------- launcher ----------------
extern "C" void kernel_launch(void* const* d_in, const int* in_sizes, int n_in,
                              void* d_out, int out_size) {
    const int*   species = (const int*)  d_in[0];
    const float* dist    = (const float*)d_in[1];
    const float* swch    = (const float*)d_in[2];
    const int*   esrc    = (const int*)  d_in[3];
    const int*   edst    = (const int*)  d_in[4];
    const float* ang     = (const float*)d_in[5];
    const float* adist   = (const float*)d_in[6];
    const float* asw     = (const float*)d_in[7];
    const int*   aedst   = (const int*)  d_in[8];
    const int*   pasrc   = (const int*)  d_in[9];
    const int*   padst   = (const int*)  d_in[10];
    const int*   catom   = (const int*)  d_in[11];
    const float* vtab    = (const float*)d_in[12];
    float* out = (float*)d_out;

    // counter clears as graph memset nodes (no allocation; capturable)
    void *p_cnt_r, *p_cnt_a, *p_task;
    cudaGetSymbolAddress(&p_cnt_r, g_cnt_r);
    cudaGetSymbolAddress(&p_cnt_a, g_cnt_a);
    cudaGetSymbolAddress(&p_task,  g_task);
    cudaMemsetAsync(p_cnt_r, 0, N_ATOMS * sizeof(int));
    cudaMemsetAsync(p_cnt_a, 0, N_ATOMS * sizeof(int));
    cudaMemsetAsync(p_task,  0, sizeof(int));

    k_prep<<<1280, 256>>>(species, vtab, aedst, adist, asw, catom, esrc);
    k_scan<<<2, 1024>>>();
    k_scatter<<<2500, 256>>>(dist, swch, esrc, edst, ang, pasrc, padst, catom);
    k_gather<<<740, 256>>>(species, out);
}

// round 16
// speedup vs baseline: 1.0023x; 1.0023x over previous
#include <cuda_runtime.h>

// ---------------- problem constants ----------------
#define N_ATOMS     20000
#define N_EDGES     640000
#define N_ANG_EDGES 160000
#define N_PAIRS     560000
#define N_FEAT      407        // 87 onehot + 64 radial + 256 angular

// ---------------- device scratch (allocation-free rule) ----------------
__device__ __align__(16) float  g_val    [N_ATOMS * 4];     // per-atom valence (320KB)
__device__ __align__(8)  float2 g_edge_ds[N_ANG_EDGES];     // {d, sw}
__device__ __align__(16) float4 g_edge_v [N_ANG_EDGES];     // valence of ang dst
__device__ int g_cnt_r [N_ATOMS];
__device__ int g_off_r [N_ATOMS + 1];
__device__ int g_cnt_a [N_ATOMS];
__device__ int g_off_a [N_ATOMS + 1];
__device__ int g_rank_r[N_EDGES];
__device__ int g_rank_a[N_PAIRS];
__device__ int g_task;
__device__ __align__(16) float4 g_pay_r[N_EDGES];           // {d, 0.25*sw, as_float(dst), 0}
__device__ __align__(16) float4 g_pay_a[N_PAIRS * 4];       // {f1[4], f2sw[4], vp[4], vm[4]}

// ---------------- kernels ----------------

// valence gather + angular-edge structs + histograms (ranks saved for scatter)
__global__ void k_prep(const int* __restrict__ species,
                       const float* __restrict__ vtab,
                       const int* __restrict__ ang_dst,
                       const float* __restrict__ ang_d,
                       const float* __restrict__ ang_sw,
                       const int* __restrict__ catom,
                       const int* __restrict__ esrc) {
    int idx = blockIdx.x * blockDim.x + threadIdx.x;
    int stride = gridDim.x * blockDim.x;
    for (int t = idx; t < N_ATOMS; t += stride) {
        int sp = species[t];
        ((float4*)g_val)[t] = *(const float4*)(vtab + sp * 4);
    }
    for (int t = idx; t < N_ANG_EDGES; t += stride) {
        int dst = ang_dst[t];
        int sp  = species[dst];
        g_edge_v[t]  = *(const float4*)(vtab + sp * 4);
        g_edge_ds[t] = make_float2(ang_d[t], ang_sw[t]);
    }
    for (int t = idx; t < N_PAIRS; t += stride)
        g_rank_a[t] = atomicAdd(&g_cnt_a[catom[t]], 1);
    for (int t = idx; t < N_EDGES; t += stride)
        g_rank_r[t] = atomicAdd(&g_cnt_r[esrc[t]], 1);
}

// two-block exclusive scan: block 0 -> radial counts, block 1 -> angular counts
__global__ void k_scan() {
    const int CHUNK = 20;                 // 1024 * 20 = 20480 >= N_ATOMS
    __shared__ int warp_sums[32];
    const int* cnt = (blockIdx.x == 0) ? g_cnt_r : g_cnt_a;
    int* off       = (blockIdx.x == 0) ? g_off_r : g_off_a;

    int t = threadIdx.x;
    int base = t * CHUNK;
    int local[CHUNK];
    int sum = 0;
    #pragma unroll
    for (int u = 0; u < CHUNK; u++) {
        int i = base + u;
        int v = (i < N_ATOMS) ? cnt[i] : 0;
        local[u] = sum;
        sum += v;
    }
    int lane = t & 31, wid = t >> 5;
    int incl = sum;
    #pragma unroll
    for (int offt = 1; offt < 32; offt <<= 1) {
        int x = __shfl_up_sync(0xFFFFFFFFu, incl, offt);
        if (lane >= offt) incl += x;
    }
    if (lane == 31) warp_sums[wid] = incl;
    __syncthreads();
    if (wid == 0) {
        int w = warp_sums[lane];
        #pragma unroll
        for (int offt = 1; offt < 32; offt <<= 1) {
            int x = __shfl_up_sync(0xFFFFFFFFu, w, offt);
            if (lane >= offt) w += x;
        }
        warp_sums[lane] = w;
    }
    __syncthreads();
    int excl_base = incl - sum + (wid > 0 ? warp_sums[wid - 1] : 0);
    #pragma unroll
    for (int u = 0; u < CHUNK; u++) {
        int i = base + u;
        if (i < N_ATOMS) off[i] = excl_base + local[u];
    }
    if (t == 1023) off[N_ATOMS] = excl_base + sum;
}

// fused scatter (no atomics): radial edges -> 16B payload, angular pairs -> 64B payload
// f2 computed with TWO expf via geometric-ratio chain (MUFU 6 -> 4 per pair):
//   xm = d12-0.8; f2[0] = exp(-8 xm^2); R = exp(10.8 xm - 3.645); Q = exp(-7.29)
//   f2[a+1] = f2[a] * R * Q^a   (algebraically identical to exp(-8(xm-0.675a)^2))
__global__ void k_scatter(const float* __restrict__ dist,
                          const float* __restrict__ swc,
                          const int* __restrict__ esrc,
                          const int* __restrict__ edst,
                          const float* __restrict__ angles,
                          const int* __restrict__ pasrc,
                          const int* __restrict__ padst,
                          const int* __restrict__ catom) {
    int idx = blockIdx.x * blockDim.x + threadIdx.x;
    int stride = gridDim.x * blockDim.x;

    // ---- radial edges: 16B payload {d, s, dst_id} ----
    for (int e = idx; e < N_EDGES; e += stride) {
        float d = dist[e];
        float s = 0.25f * swc[e];
        int a   = esrc[e];
        int pos = g_off_r[a] + g_rank_r[e];
        g_pay_r[pos] = make_float4(d, s, __int_as_float(edst[e]), 0.f);
    }

    // ---- angular pairs: 64B payload ----
    for (int p = idx; p < N_PAIRS; p += stride) {
        int ea = pasrc[p];
        int eb = padst[p];
        float2 Ads = g_edge_ds[ea];
        float2 Bds = g_edge_ds[eb];
        float4 Av  = g_edge_v[ea];
        float4 Bv  = g_edge_v[eb];

        float d12 = 0.5f * (Ads.x + Bds.x);
        float swp = 2.0f * Ads.y * Bds.y;

        float sn, cs;
        __sincosf(angles[p], &sn, &cs);
        const float CZ[4] = { 0.92387953f,  0.38268343f, -0.38268343f, -0.92387953f};
        const float SZ[4] = { 0.38268343f,  0.92387953f,  0.92387953f,  0.38268343f};
        float f1[4];
        #pragma unroll
        for (int k = 0; k < 4; k++) {
            float u = 0.5f + 0.5f * (cs * CZ[k] + sn * SZ[k]);
            float u2 = u * u, u4 = u2 * u2, u8 = u4 * u4, u16 = u8 * u8;
            f1[k] = u16 * u16;
        }
        // f2 * swp via 2-exp ratio chain
        float xm = d12 - 0.8f;
        const float Q = 6.82328e-4f;                 // exp(-7.29)
        float f2_0 = swp * __expf(-8.0f * xm * xm);
        float R    = __expf(fmaf(10.8f, xm, -3.645f));
        float RQ   = R * Q;
        float f2_1 = f2_0 * R;
        float f2_2 = f2_1 * RQ;
        float f2_3 = f2_2 * (RQ * Q);

        int c = catom[p];
        int pos = g_off_a[c] + g_rank_a[p];
        float4* P = g_pay_a + pos * 4;
        P[0] = make_float4(f1[0], f1[1], f1[2], f1[3]);
        P[1] = make_float4(f2_0, f2_1, f2_2, f2_3);
        P[2] = make_float4(Av.x + Bv.x, Av.y + Bv.y, Av.z + Bv.z, Av.w + Bv.w);
        P[3] = make_float4(Av.x * Bv.x, Av.y * Bv.y, Av.z * Bv.z, Av.w * Bv.w);
    }
}

// fused gather: warp-per-atom, dynamic queue, pointer-walking loops.
// Radial: full-warp broadcast, 3x batched.
// Angular: split-warp (half g handles pairs g, g+2, ...), 2x-batched pointer
//   walk with immediate-offset loads; lane t=lane&15 covers vcombo (ii,jj) for
//   all 16 cells; merged via shfl_xor(16); lane (g,t) writes cells
//   [g*8,g*8+8) at col 151 + c*16 + t.   (round-13 proven form)
__global__ void __launch_bounds__(256, 5) k_gather(const int* __restrict__ species,
                                                   float* __restrict__ out) {
    int lane = threadIdx.x & 31;
    int g  = lane >> 4;
    int t  = lane & 15;
    int ii = t >> 2;
    int jj = t & 3;
    int iq = lane & 3;
    float sh1 = 0.8f + 0.275f * (float)(lane >> 2);
    float sh2 = sh1 + 2.2f;                          // +8 bins * 0.275

    for (;;) {
        int a;
        if (lane == 0) a = atomicAdd(&g_task, 1);
        a = __shfl_sync(0xFFFFFFFFu, a, 0);
        if (a >= N_ATOMS) return;

        float* o = out + (size_t)a * N_FEAT;

        // ---- onehot ----
        int sp = species[a];
        for (int c = lane; c < 87; c += 32) o[c] = (c == sp) ? 1.0f : 0.0f;

        // ---- radial: cols 87..150 (pointer walk, 3x batch) ----
        int s0 = g_off_r[a];
        int n0 = g_off_r[a + 1] - s0;
        const float4* rp = g_pay_r + s0;
        float acc0 = 0.f, acc1 = 0.f;
        int p = 0;
        for (; p + 3 <= n0; p += 3, rp += 3) {
            float4 Pa = rp[0];
            float4 Pb = rp[1];
            float4 Pc = rp[2];
            float va = g_val[__float_as_int(Pa.z) * 4 + iq];
            float vb = g_val[__float_as_int(Pb.z) * 4 + iq];
            float vc = g_val[__float_as_int(Pc.z) * 4 + iq];
            float xa1 = Pa.x - sh1, xa2 = Pa.x - sh2;
            float xb1 = Pb.x - sh1, xb2 = Pb.x - sh2;
            float xc1 = Pc.x - sh1, xc2 = Pc.x - sh2;
            acc0 = fmaf(Pa.y * __expf(-16.f * xa1 * xa1), va, acc0);
            acc1 = fmaf(Pa.y * __expf(-16.f * xa2 * xa2), va, acc1);
            acc0 = fmaf(Pb.y * __expf(-16.f * xb1 * xb1), vb, acc0);
            acc1 = fmaf(Pb.y * __expf(-16.f * xb2 * xb2), vb, acc1);
            acc0 = fmaf(Pc.y * __expf(-16.f * xc1 * xc1), vc, acc0);
            acc1 = fmaf(Pc.y * __expf(-16.f * xc2 * xc2), vc, acc1);
        }
        for (; p < n0; p++, rp++) {
            float4 Pa = rp[0];
            float va = g_val[__float_as_int(Pa.z) * 4 + iq];
            float xa1 = Pa.x - sh1, xa2 = Pa.x - sh2;
            acc0 = fmaf(Pa.y * __expf(-16.f * xa1 * xa1), va, acc0);
            acc1 = fmaf(Pa.y * __expf(-16.f * xa2 * xa2), va, acc1);
        }
        o[87 + lane]  = acc0;
        o[119 + lane] = acc1;

        // ---- angular: cols 151..406 (split-warp, 2x batch, immediate offsets) ----
        int s1 = g_off_a[a];
        int n1 = g_off_a[a + 1] - s1;
        float acc[16];
        #pragma unroll
        for (int c = 0; c < 16; c++) acc[c] = 0.f;

        // half g processes pairs g, g+2, ... : cnt = ceil((n1-g)/2)
        int cnt = (n1 - g + 1) >> 1;
        const float* bp = (const float*)g_pay_a + ((size_t)(s1 + g) << 4);
        int it = 0;
        for (; it + 2 <= cnt; it += 2, bp += 64) {
            // pair A at bp[0..15], pair B at bp[32..47] — all immediate offsets
            float4 F1a = *(const float4*)(bp);
            float4 F2a = *(const float4*)(bp + 4);
            float  vpa = bp[8 + ii];
            float  vma = bp[12 + jj];
            float4 F1b = *(const float4*)(bp + 32);
            float4 F2b = *(const float4*)(bp + 36);
            float  vpb = bp[40 + ii];
            float  vmb = bp[44 + jj];

            float wva = vpa * vma;
            float a0 = wva * F1a.x, a1 = wva * F1a.y, a2 = wva * F1a.z, a3 = wva * F1a.w;
            acc[ 0] = fmaf(a0, F2a.x, acc[ 0]);
            acc[ 1] = fmaf(a1, F2a.x, acc[ 1]);
            acc[ 2] = fmaf(a2, F2a.x, acc[ 2]);
            acc[ 3] = fmaf(a3, F2a.x, acc[ 3]);
            acc[ 4] = fmaf(a0, F2a.y, acc[ 4]);
            acc[ 5] = fmaf(a1, F2a.y, acc[ 5]);
            acc[ 6] = fmaf(a2, F2a.y, acc[ 6]);
            acc[ 7] = fmaf(a3, F2a.y, acc[ 7]);
            acc[ 8] = fmaf(a0, F2a.z, acc[ 8]);
            acc[ 9] = fmaf(a1, F2a.z, acc[ 9]);
            acc[10] = fmaf(a2, F2a.z, acc[10]);
            acc[11] = fmaf(a3, F2a.z, acc[11]);
            acc[12] = fmaf(a0, F2a.w, acc[12]);
            acc[13] = fmaf(a1, F2a.w, acc[13]);
            acc[14] = fmaf(a2, F2a.w, acc[14]);
            acc[15] = fmaf(a3, F2a.w, acc[15]);

            float wvb = vpb * vmb;
            float b0 = wvb * F1b.x, b1 = wvb * F1b.y, b2 = wvb * F1b.z, b3 = wvb * F1b.w;
            acc[ 0] = fmaf(b0, F2b.x, acc[ 0]);
            acc[ 1] = fmaf(b1, F2b.x, acc[ 1]);
            acc[ 2] = fmaf(b2, F2b.x, acc[ 2]);
            acc[ 3] = fmaf(b3, F2b.x, acc[ 3]);
            acc[ 4] = fmaf(b0, F2b.y, acc[ 4]);
            acc[ 5] = fmaf(b1, F2b.y, acc[ 5]);
            acc[ 6] = fmaf(b2, F2b.y, acc[ 6]);
            acc[ 7] = fmaf(b3, F2b.y, acc[ 7]);
            acc[ 8] = fmaf(b0, F2b.z, acc[ 8]);
            acc[ 9] = fmaf(b1, F2b.z, acc[ 9]);
            acc[10] = fmaf(b2, F2b.z, acc[10]);
            acc[11] = fmaf(b3, F2b.z, acc[11]);
            acc[12] = fmaf(b0, F2b.w, acc[12]);
            acc[13] = fmaf(b1, F2b.w, acc[13]);
            acc[14] = fmaf(b2, F2b.w, acc[14]);
            acc[15] = fmaf(b3, F2b.w, acc[15]);
        }
        for (; it < cnt; it++, bp += 32) {
            float4 F1 = *(const float4*)bp;
            float4 F2 = *(const float4*)(bp + 4);
            float wv = bp[8 + ii] * bp[12 + jj];
            float w0 = wv * F1.x, w1 = wv * F1.y, w2 = wv * F1.z, w3 = wv * F1.w;
            acc[ 0] = fmaf(w0, F2.x, acc[ 0]);
            acc[ 1] = fmaf(w1, F2.x, acc[ 1]);
            acc[ 2] = fmaf(w2, F2.x, acc[ 2]);
            acc[ 3] = fmaf(w3, F2.x, acc[ 3]);
            acc[ 4] = fmaf(w0, F2.y, acc[ 4]);
            acc[ 5] = fmaf(w1, F2.y, acc[ 5]);
            acc[ 6] = fmaf(w2, F2.y, acc[ 6]);
            acc[ 7] = fmaf(w3, F2.y, acc[ 7]);
            acc[ 8] = fmaf(w0, F2.z, acc[ 8]);
            acc[ 9] = fmaf(w1, F2.z, acc[ 9]);
            acc[10] = fmaf(w2, F2.z, acc[10]);
            acc[11] = fmaf(w3, F2.z, acc[11]);
            acc[12] = fmaf(w0, F2.w, acc[12]);
            acc[13] = fmaf(w1, F2.w, acc[13]);
            acc[14] = fmaf(w2, F2.w, acc[14]);
            acc[15] = fmaf(w3, F2.w, acc[15]);
        }
        // merge halves (lanes reconverged after loop)
        #pragma unroll
        for (int c = 0; c < 16; c++)
            acc[c] += __shfl_xor_sync(0xFFFFFFFFu, acc[c], 16);
        // lane (g,t) writes cells c in [g*8, g*8+8): col 151 + c*16 + t
        #pragma unroll
        for (int c2 = 0; c2 < 8; c2++) {
            int c = g * 8 + c2;
            o[151 + c * 16 + t] = acc[c];
        }
    }
}

// ---------------- launcher ----------------
extern "C" void kernel_launch(void* const* d_in, const int* in_sizes, int n_in,
                              void* d_out, int out_size) {
    const int*   species = (const int*)  d_in[0];
    const float* dist    = (const float*)d_in[1];
    const float* swch    = (const float*)d_in[2];
    const int*   esrc    = (const int*)  d_in[3];
    const int*   edst    = (const int*)  d_in[4];
    const float* ang     = (const float*)d_in[5];
    const float* adist   = (const float*)d_in[6];
    const float* asw     = (const float*)d_in[7];
    const int*   aedst   = (const int*)  d_in[8];
    const int*   pasrc   = (const int*)  d_in[9];
    const int*   padst   = (const int*)  d_in[10];
    const int*   catom   = (const int*)  d_in[11];
    const float* vtab    = (const float*)d_in[12];
    float* out = (float*)d_out;

    // counter clears as graph memset nodes (no allocation; capturable)
    void *p_cnt_r, *p_cnt_a, *p_task;
    cudaGetSymbolAddress(&p_cnt_r, g_cnt_r);
    cudaGetSymbolAddress(&p_cnt_a, g_cnt_a);
    cudaGetSymbolAddress(&p_task,  g_task);
    cudaMemsetAsync(p_cnt_r, 0, N_ATOMS * sizeof(int));
    cudaMemsetAsync(p_cnt_a, 0, N_ATOMS * sizeof(int));
    cudaMemsetAsync(p_task,  0, sizeof(int));

    k_prep<<<1280, 256>>>(species, vtab, aedst, adist, asw, catom, esrc);
    k_scan<<<2, 1024>>>();
    k_scatter<<<2500, 256>>>(dist, swch, esrc, edst, ang, pasrc, padst, catom);
    k_gather<<<740, 256>>>(species, out);
}

// round 17
// speedup vs baseline: 1.0512x; 1.0487x over previous
#include <cuda_runtime.h>

// ---------------- problem constants ----------------
#define N_ATOMS     20000
#define N_EDGES     640000
#define N_ANG_EDGES 160000
#define N_PAIRS     560000
#define N_FEAT      407        // 87 onehot + 64 radial + 256 angular

// ---------------- device scratch (allocation-free rule) ----------------
__device__ __align__(16) float  g_val  [N_ATOMS * 4];       // per-atom valence (320KB)
__device__ __align__(16) float4 g_edge [N_ANG_EDGES * 2];   // {d, sw, v0, v1} {v2, v3, -, -} 32B record
__device__ int g_cnt  [2 * N_ATOMS + 1];                    // [0,N): radial, [N,2N): angular, [2N]: task
__device__ int g_off_r[N_ATOMS + 1];
__device__ int g_off_a[N_ATOMS + 1];
__device__ int g_rank_r[N_EDGES];
__device__ int g_rank_a[N_PAIRS];
__device__ __align__(16) float4 g_pay_r[N_EDGES];           // {d, 0.25*sw, as_float(dst), 0}
__device__ __align__(16) float4 g_pay_a[N_PAIRS * 4];       // {f1[4], f2sw[4], vp[4], vm[4]}

// ---------------- kernels ----------------

// valence gather + angular-edge structs + histograms (ranks saved) + onehot
__global__ void k_prep(const int* __restrict__ species,
                       const float* __restrict__ vtab,
                       const int* __restrict__ ang_dst,
                       const float* __restrict__ ang_d,
                       const float* __restrict__ ang_sw,
                       const int* __restrict__ catom,
                       const int* __restrict__ esrc,
                       float* __restrict__ out) {
    int idx = blockIdx.x * blockDim.x + threadIdx.x;
    int stride = gridDim.x * blockDim.x;
    for (int t = idx; t < N_ATOMS; t += stride) {
        int sp = species[t];
        ((float4*)g_val)[t] = *(const float4*)(vtab + sp * 4);
    }
    for (int t = idx; t < N_ANG_EDGES; t += stride) {
        int dst = ang_dst[t];
        int sp  = species[dst];
        float4 v = *(const float4*)(vtab + sp * 4);
        g_edge[t * 2 + 0] = make_float4(ang_d[t], ang_sw[t], v.x, v.y);
        g_edge[t * 2 + 1] = make_float4(v.z, v.w, 0.f, 0.f);
    }
    for (int t = idx; t < N_PAIRS; t += stride)
        g_rank_a[t] = atomicAdd(&g_cnt[N_ATOMS + catom[t]], 1);
    for (int t = idx; t < N_EDGES; t += stride)
        g_rank_r[t] = atomicAdd(&g_cnt[esrc[t]], 1);

    // onehot: warp-per-atom (cols 0..86 of out)
    int gwarp  = idx >> 5;
    int nwarps = stride >> 5;
    int lane   = threadIdx.x & 31;
    for (int a = gwarp; a < N_ATOMS; a += nwarps) {
        int sp = species[a];
        float* o = out + (size_t)a * N_FEAT;
        #pragma unroll
        for (int c = lane; c < 87; c += 32) o[c] = (c == sp) ? 1.0f : 0.0f;
    }
}

// two-block exclusive scan: block 0 -> radial counts, block 1 -> angular counts
__global__ void k_scan() {
    const int CHUNK = 20;                 // 1024 * 20 = 20480 >= N_ATOMS
    __shared__ int warp_sums[32];
    const int* cnt = (blockIdx.x == 0) ? g_cnt : (g_cnt + N_ATOMS);
    int* off       = (blockIdx.x == 0) ? g_off_r : g_off_a;

    int t = threadIdx.x;
    int base = t * CHUNK;
    int local[CHUNK];
    int sum = 0;
    #pragma unroll
    for (int u = 0; u < CHUNK; u++) {
        int i = base + u;
        int v = (i < N_ATOMS) ? cnt[i] : 0;
        local[u] = sum;
        sum += v;
    }
    int lane = t & 31, wid = t >> 5;
    int incl = sum;
    #pragma unroll
    for (int offt = 1; offt < 32; offt <<= 1) {
        int x = __shfl_up_sync(0xFFFFFFFFu, incl, offt);
        if (lane >= offt) incl += x;
    }
    if (lane == 31) warp_sums[wid] = incl;
    __syncthreads();
    if (wid == 0) {
        int w = warp_sums[lane];
        #pragma unroll
        for (int offt = 1; offt < 32; offt <<= 1) {
            int x = __shfl_up_sync(0xFFFFFFFFu, w, offt);
            if (lane >= offt) w += x;
        }
        warp_sums[lane] = w;
    }
    __syncthreads();
    int excl_base = incl - sum + (wid > 0 ? warp_sums[wid - 1] : 0);
    #pragma unroll
    for (int u = 0; u < CHUNK; u++) {
        int i = base + u;
        if (i < N_ATOMS) off[i] = excl_base + local[u];
    }
    if (t == 1023) off[N_ATOMS] = excl_base + sum;
}

// fused scatter (no atomics): radial edges -> 16B payload, angular pairs -> 64B payload
// Angular edge record is ONE 32B struct -> 2 random lines per pair instead of 4.
// f2 via 2-exp geometric-ratio chain (kept; verified correct).
__global__ void k_scatter(const float* __restrict__ dist,
                          const float* __restrict__ swc,
                          const int* __restrict__ esrc,
                          const int* __restrict__ edst,
                          const float* __restrict__ angles,
                          const int* __restrict__ pasrc,
                          const int* __restrict__ padst,
                          const int* __restrict__ catom) {
    int idx = blockIdx.x * blockDim.x + threadIdx.x;
    int stride = gridDim.x * blockDim.x;

    // ---- radial edges: 16B payload {d, s, dst_id} ----
    for (int e = idx; e < N_EDGES; e += stride) {
        float d = dist[e];
        float s = 0.25f * swc[e];
        int a   = esrc[e];
        int pos = g_off_r[a] + g_rank_r[e];
        g_pay_r[pos] = make_float4(d, s, __int_as_float(edst[e]), 0.f);
    }

    // ---- angular pairs: 64B payload ----
    for (int p = idx; p < N_PAIRS; p += stride) {
        int ea = pasrc[p];
        int eb = padst[p];
        float4 A0 = g_edge[ea * 2 + 0];
        float4 A1 = g_edge[ea * 2 + 1];
        float4 B0 = g_edge[eb * 2 + 0];
        float4 B1 = g_edge[eb * 2 + 1];

        float d12 = 0.5f * (A0.x + B0.x);
        float swp = 2.0f * A0.y * B0.y;

        float sn, cs;
        __sincosf(angles[p], &sn, &cs);
        const float CZ[4] = { 0.92387953f,  0.38268343f, -0.38268343f, -0.92387953f};
        const float SZ[4] = { 0.38268343f,  0.92387953f,  0.92387953f,  0.38268343f};
        float f1[4];
        #pragma unroll
        for (int k = 0; k < 4; k++) {
            float u = 0.5f + 0.5f * (cs * CZ[k] + sn * SZ[k]);
            float u2 = u * u, u4 = u2 * u2, u8 = u4 * u4, u16 = u8 * u8;
            f1[k] = u16 * u16;
        }
        // f2 * swp via 2-exp ratio chain
        float xm = d12 - 0.8f;
        const float Q = 6.82328e-4f;                 // exp(-7.29)
        float f2_0 = swp * __expf(-8.0f * xm * xm);
        float R    = __expf(fmaf(10.8f, xm, -3.645f));
        float RQ   = R * Q;
        float f2_1 = f2_0 * R;
        float f2_2 = f2_1 * RQ;
        float f2_3 = f2_2 * (RQ * Q);

        int c = catom[p];
        int pos = g_off_a[c] + g_rank_a[p];
        float4* P = g_pay_a + pos * 4;
        P[0] = make_float4(f1[0], f1[1], f1[2], f1[3]);
        P[1] = make_float4(f2_0, f2_1, f2_2, f2_3);
        P[2] = make_float4(A0.z + B0.z, A0.w + B0.w, A1.x + B1.x, A1.y + B1.y);
        P[3] = make_float4(A0.z * B0.z, A0.w * B0.w, A1.x * B1.x, A1.y * B1.y);
    }
}

// fused gather: warp-per-atom, dynamic queue, pointer-walking loops.
// Radial: full-warp broadcast, 3x batched.
// Angular: split-warp (half g handles pairs g, g+2, ...), 2x-batched pointer
//   walk with immediate-offset loads; lane t=lane&15 covers vcombo (ii,jj) for
//   all 16 cells; merged via shfl_xor(16); lane (g,t) writes cells
//   [g*8,g*8+8) at col 151 + c*16 + t.   (round-13 proven form; onehot moved to prep)
__global__ void __launch_bounds__(256, 5) k_gather(float* __restrict__ out) {
    int lane = threadIdx.x & 31;
    int g  = lane >> 4;
    int t  = lane & 15;
    int ii = t >> 2;
    int jj = t & 3;
    int iq = lane & 3;
    float sh1 = 0.8f + 0.275f * (float)(lane >> 2);
    float sh2 = sh1 + 2.2f;                          // +8 bins * 0.275

    for (;;) {
        int a;
        if (lane == 0) a = atomicAdd(&g_cnt[2 * N_ATOMS], 1);
        a = __shfl_sync(0xFFFFFFFFu, a, 0);
        if (a >= N_ATOMS) return;

        float* o = out + (size_t)a * N_FEAT;

        // ---- radial: cols 87..150 (pointer walk, 3x batch) ----
        int s0 = g_off_r[a];
        int n0 = g_off_r[a + 1] - s0;
        const float4* rp = g_pay_r + s0;
        float acc0 = 0.f, acc1 = 0.f;
        int p = 0;
        for (; p + 3 <= n0; p += 3, rp += 3) {
            float4 Pa = rp[0];
            float4 Pb = rp[1];
            float4 Pc = rp[2];
            float va = g_val[__float_as_int(Pa.z) * 4 + iq];
            float vb = g_val[__float_as_int(Pb.z) * 4 + iq];
            float vc = g_val[__float_as_int(Pc.z) * 4 + iq];
            float xa1 = Pa.x - sh1, xa2 = Pa.x - sh2;
            float xb1 = Pb.x - sh1, xb2 = Pb.x - sh2;
            float xc1 = Pc.x - sh1, xc2 = Pc.x - sh2;
            acc0 = fmaf(Pa.y * __expf(-16.f * xa1 * xa1), va, acc0);
            acc1 = fmaf(Pa.y * __expf(-16.f * xa2 * xa2), va, acc1);
            acc0 = fmaf(Pb.y * __expf(-16.f * xb1 * xb1), vb, acc0);
            acc1 = fmaf(Pb.y * __expf(-16.f * xb2 * xb2), vb, acc1);
            acc0 = fmaf(Pc.y * __expf(-16.f * xc1 * xc1), vc, acc0);
            acc1 = fmaf(Pc.y * __expf(-16.f * xc2 * xc2), vc, acc1);
        }
        for (; p < n0; p++, rp++) {
            float4 Pa = rp[0];
            float va = g_val[__float_as_int(Pa.z) * 4 + iq];
            float xa1 = Pa.x - sh1, xa2 = Pa.x - sh2;
            acc0 = fmaf(Pa.y * __expf(-16.f * xa1 * xa1), va, acc0);
            acc1 = fmaf(Pa.y * __expf(-16.f * xa2 * xa2), va, acc1);
        }
        o[87 + lane]  = acc0;
        o[119 + lane] = acc1;

        // ---- angular: cols 151..406 (split-warp, 2x batch, immediate offsets) ----
        int s1 = g_off_a[a];
        int n1 = g_off_a[a + 1] - s1;
        float acc[16];
        #pragma unroll
        for (int c = 0; c < 16; c++) acc[c] = 0.f;

        // half g processes pairs g, g+2, ... : cnt = ceil((n1-g)/2)
        int cnt = (n1 - g + 1) >> 1;
        const float* bp = (const float*)g_pay_a + ((size_t)(s1 + g) << 4);
        int it = 0;
        for (; it + 2 <= cnt; it += 2, bp += 64) {
            // pair A at bp[0..15], pair B at bp[32..47] — all immediate offsets
            float4 F1a = *(const float4*)(bp);
            float4 F2a = *(const float4*)(bp + 4);
            float  vpa = bp[8 + ii];
            float  vma = bp[12 + jj];
            float4 F1b = *(const float4*)(bp + 32);
            float4 F2b = *(const float4*)(bp + 36);
            float  vpb = bp[40 + ii];
            float  vmb = bp[44 + jj];

            float wva = vpa * vma;
            float a0 = wva * F1a.x, a1 = wva * F1a.y, a2 = wva * F1a.z, a3 = wva * F1a.w;
            acc[ 0] = fmaf(a0, F2a.x, acc[ 0]);
            acc[ 1] = fmaf(a1, F2a.x, acc[ 1]);
            acc[ 2] = fmaf(a2, F2a.x, acc[ 2]);
            acc[ 3] = fmaf(a3, F2a.x, acc[ 3]);
            acc[ 4] = fmaf(a0, F2a.y, acc[ 4]);
            acc[ 5] = fmaf(a1, F2a.y, acc[ 5]);
            acc[ 6] = fmaf(a2, F2a.y, acc[ 6]);
            acc[ 7] = fmaf(a3, F2a.y, acc[ 7]);
            acc[ 8] = fmaf(a0, F2a.z, acc[ 8]);
            acc[ 9] = fmaf(a1, F2a.z, acc[ 9]);
            acc[10] = fmaf(a2, F2a.z, acc[10]);
            acc[11] = fmaf(a3, F2a.z, acc[11]);
            acc[12] = fmaf(a0, F2a.w, acc[12]);
            acc[13] = fmaf(a1, F2a.w, acc[13]);
            acc[14] = fmaf(a2, F2a.w, acc[14]);
            acc[15] = fmaf(a3, F2a.w, acc[15]);

            float wvb = vpb * vmb;
            float b0 = wvb * F1b.x, b1 = wvb * F1b.y, b2 = wvb * F1b.z, b3 = wvb * F1b.w;
            acc[ 0] = fmaf(b0, F2b.x, acc[ 0]);
            acc[ 1] = fmaf(b1, F2b.x, acc[ 1]);
            acc[ 2] = fmaf(b2, F2b.x, acc[ 2]);
            acc[ 3] = fmaf(b3, F2b.x, acc[ 3]);
            acc[ 4] = fmaf(b0, F2b.y, acc[ 4]);
            acc[ 5] = fmaf(b1, F2b.y, acc[ 5]);
            acc[ 6] = fmaf(b2, F2b.y, acc[ 6]);
            acc[ 7] = fmaf(b3, F2b.y, acc[ 7]);
            acc[ 8] = fmaf(b0, F2b.z, acc[ 8]);
            acc[ 9] = fmaf(b1, F2b.z, acc[ 9]);
            acc[10] = fmaf(b2, F2b.z, acc[10]);
            acc[11] = fmaf(b3, F2b.z, acc[11]);
            acc[12] = fmaf(b0, F2b.w, acc[12]);
            acc[13] = fmaf(b1, F2b.w, acc[13]);
            acc[14] = fmaf(b2, F2b.w, acc[14]);
            acc[15] = fmaf(b3, F2b.w, acc[15]);
        }
        for (; it < cnt; it++, bp += 32) {
            float4 F1 = *(const float4*)bp;
            float4 F2 = *(const float4*)(bp + 4);
            float wv = bp[8 + ii] * bp[12 + jj];
            float w0 = wv * F1.x, w1 = wv * F1.y, w2 = wv * F1.z, w3 = wv * F1.w;
            acc[ 0] = fmaf(w0, F2.x, acc[ 0]);
            acc[ 1] = fmaf(w1, F2.x, acc[ 1]);
            acc[ 2] = fmaf(w2, F2.x, acc[ 2]);
            acc[ 3] = fmaf(w3, F2.x, acc[ 3]);
            acc[ 4] = fmaf(w0, F2.y, acc[ 4]);
            acc[ 5] = fmaf(w1, F2.y, acc[ 5]);
            acc[ 6] = fmaf(w2, F2.y, acc[ 6]);
            acc[ 7] = fmaf(w3, F2.y, acc[ 7]);
            acc[ 8] = fmaf(w0, F2.z, acc[ 8]);
            acc[ 9] = fmaf(w1, F2.z, acc[ 9]);
            acc[10] = fmaf(w2, F2.z, acc[10]);
            acc[11] = fmaf(w3, F2.z, acc[11]);
            acc[12] = fmaf(w0, F2.w, acc[12]);
            acc[13] = fmaf(w1, F2.w, acc[13]);
            acc[14] = fmaf(w2, F2.w, acc[14]);
            acc[15] = fmaf(w3, F2.w, acc[15]);
        }
        // merge halves (lanes reconverged after loop)
        #pragma unroll
        for (int c = 0; c < 16; c++)
            acc[c] += __shfl_xor_sync(0xFFFFFFFFu, acc[c], 16);
        // lane (g,t) writes cells c in [g*8, g*8+8): col 151 + c*16 + t
        #pragma unroll
        for (int c2 = 0; c2 < 8; c2++) {
            int c = g * 8 + c2;
            o[151 + c * 16 + t] = acc[c];
        }
    }
}

// ---------------- launcher ----------------
extern "C" void kernel_launch(void* const* d_in, const int* in_sizes, int n_in,
                              void* d_out, int out_size) {
    const int*   species = (const int*)  d_in[0];
    const float* dist    = (const float*)d_in[1];
    const float* swch    = (const float*)d_in[2];
    const int*   esrc    = (const int*)  d_in[3];
    const int*   edst    = (const int*)  d_in[4];
    const float* ang     = (const float*)d_in[5];
    const float* adist   = (const float*)d_in[6];
    const float* asw     = (const float*)d_in[7];
    const int*   aedst   = (const int*)  d_in[8];
    const int*   pasrc   = (const int*)  d_in[9];
    const int*   padst   = (const int*)  d_in[10];
    const int*   catom   = (const int*)  d_in[11];
    const float* vtab    = (const float*)d_in[12];
    float* out = (float*)d_out;

    // single counter clear (radial hist + angular hist + task) as one memset node
    void* p_cnt;
    cudaGetSymbolAddress(&p_cnt, g_cnt);
    cudaMemsetAsync(p_cnt, 0, (2 * N_ATOMS + 1) * sizeof(int));

    k_prep<<<1280, 256>>>(species, vtab, aedst, adist, asw, catom, esrc, out);
    k_scan<<<2, 1024>>>();
    k_scatter<<<2500, 256>>>(dist, swch, esrc, edst, ang, pasrc, padst, catom);
    k_gather<<<740, 256>>>(out);
}